// round 1
// baseline (speedup 1.0000x reference)
#include <cuda_runtime.h>
#include <cstdint>

// ---------------------------------------------------------------------------
// RowLSTM: i_s precompute (7x7 convs) -> sequential row scan (LSTM) -> 1x1 out
//
// Decomposition:
//   kA: i_s [B][H][160][W]  (two 7x7 convs, one masked), SMEM-tiled
//   kB: the scan. 16 clusters of 8 CTAs (one cluster per batch, each CTA owns
//       8 w-positions). Per row: exchange 1 boundary column of (h,c) between
//       neighbor CTAs via global parity buffers + barrier.cluster, then
//       row-convs + 7 LSTM layers entirely CTA-local (1x1 convs are
//       per-position). All weights resident in SMEM (~222 KB).
//   kC: out = relu(W_out @ hidden + b), per-(b,y) blocks.
// ---------------------------------------------------------------------------

#define HIDDEN   40
#define NLAYERS  7
#define BATCH    16
#define HH       64
#define WW       64
#define CPB      8      // CTAs per batch (cluster size)
#define WPC      8      // w positions per CTA
#define TPB_B    320    // 40 hc * 8 w

// ---------------- scratch (static device memory; no allocations) -----------
__device__ float g_is[(size_t)BATCH * HH * 160 * WW];          // 41.9 MB
__device__ float g_hidden[(size_t)BATCH * HH * HIDDEN * WW];   // 10.5 MB
// [parity][b][crank][side 0=left/1=right][0=h/1=c][hc]
__device__ float g_exp[2][BATCH][CPB][2][2][HIDDEN];

// ---------------- helpers ---------------------------------------------------
__device__ __forceinline__ float sigf(float x) {
    float e = __expf(-x);
    return __fdividef(1.0f, 1.0f + e);
}
__device__ __forceinline__ float tanhf_fast(float x) {
    float ax = fabsf(x);
    float e = __expf(2.0f * ax);
    float t = 1.0f - __fdividef(2.0f, e + 1.0f);
    return copysignf(t, x);
}
__device__ __forceinline__ float dot4(float4 a, float4 b) {
    return a.x * b.x + a.y * b.y + a.z * b.z + a.w * b.w;
}
__device__ __forceinline__ void cluster_sync_() {
    asm volatile("barrier.cluster.arrive.aligned;" ::: "memory");
    asm volatile("barrier.cluster.wait.aligned;" ::: "memory");
}

// ===========================================================================
// Kernel A: i_s = [conv_i_s(input)+b_cis ; masked_conv(target)+b_is]
// grid (4,4,16) tiles of 16x16, 256 threads
// ===========================================================================
__global__ void __launch_bounds__(256) kA(
    const float* __restrict__ inp, const float* __restrict__ tgt,
    const float* __restrict__ w_is, const float* __restrict__ b_is,
    const float* __restrict__ w_cis, const float* __restrict__ b_cis)
{
    __shared__ float sW[160 * 52];   // weights padded to 52 taps (3 zero)
    __shared__ float sB[160];
    __shared__ float sT[22][22];

    const int b   = blockIdx.z;
    const int ty0 = blockIdx.y * 16;
    const int tx0 = blockIdx.x * 16;
    const int tid = threadIdx.x;
    const int ty  = tid / 16;
    const int tx  = tid % 16;

    // stage weights (mask applied to target conv: keep r<3 all s, r==3 s<3)
    for (int i = tid; i < 160 * 52; i += 256) {
        int oc = i / 52, j = i % 52;
        float v = 0.0f;
        if (j < 49) {
            int r = j / 7, s = j % 7;
            if (oc < 80) {
                v = w_cis[oc * 49 + j];
            } else {
                bool keep = (r < 3) || (r == 3 && s < 3);
                v = keep ? w_is[(oc - 80) * 49 + j] : 0.0f;
            }
        }
        sW[i] = v;
    }
    for (int i = tid; i < 160; i += 256)
        sB[i] = (i < 80) ? b_cis[i] : b_is[i - 80];

    for (int pass = 0; pass < 2; ++pass) {
        __syncthreads();
        const float* src = pass ? tgt : inp;
        for (int i = tid; i < 22 * 22; i += 256) {
            int r = i / 22, cc = i % 22;
            int y = ty0 - 3 + r, x = tx0 - 3 + cc;
            sT[r][cc] = (y >= 0 && y < HH && x >= 0 && x < WW)
                            ? src[((size_t)b * HH + y) * WW + x] : 0.0f;
        }
        __syncthreads();

        float v[52];
#pragma unroll
        for (int r = 0; r < 7; ++r)
#pragma unroll
            for (int s = 0; s < 7; ++s)
                v[r * 7 + s] = sT[ty + r][tx + s];
        v[49] = 0.0f; v[50] = 0.0f; v[51] = 0.0f;

        const int ocbase = pass * 80;
        for (int oc = ocbase; oc < ocbase + 80; ++oc) {
            float a = sB[oc];
            const float4* w4 = (const float4*)&sW[oc * 52];
#pragma unroll
            for (int jj = 0; jj < 13; ++jj) {
                float4 W = w4[jj];
                a += W.x * v[4 * jj + 0] + W.y * v[4 * jj + 1]
                   + W.z * v[4 * jj + 2] + W.w * v[4 * jj + 3];
            }
            g_is[(((size_t)b * HH + (ty0 + ty)) * 160 + oc) * WW + (tx0 + tx)] = a;
        }
    }
}

// ===========================================================================
// Kernel B: the scan. grid = 128 CTAs (16 clusters of 8), 320 threads.
// thread (hc = tid>>3, w = tid&7) owns hidden channel hc at local position w.
// SMEM (floats): wc 44800 | wr 9600 | bc 1120 | br 80 | Ha 400 | Hb 400 | C 400
// ===========================================================================
#define SMEMB_FLOATS (44800 + 9600 + 1120 + 80 + 400 + 400 + 400)
#define SMEMB_BYTES  (SMEMB_FLOATS * 4)

__global__ void __cluster_dims__(CPB, 1, 1) __launch_bounds__(TPB_B, 1) kB(
    const float* __restrict__ w_cell, const float* __restrict__ b_cell,
    const float* __restrict__ w_rh, const float* __restrict__ b_rh,
    const float* __restrict__ w_rc, const float* __restrict__ b_rc)
{
    extern __shared__ float sm[];
    float* sWc = sm;                 // [7][160][40]
    float* sWr = sWc + 44800;        // [2][40 oc][3 tap][40 ic]
    float* sBc = sWr + 9600;         // [7][160]
    float* sBr = sBc + 1120;         // [2][40]
    float* sHa = sBr + 80;           // [10][40]  (w-ext major, cols 0/9 = halo)
    float* sHb = sHa + 400;          // [10][40]
    float* sC  = sHb + 400;          // [10][40]

    const int tid   = threadIdx.x;
    const int hc    = tid >> 3;
    const int w     = tid & 7;
    const int b     = blockIdx.x >> 3;
    const int crank = blockIdx.x & 7;
    const int wg    = crank * WPC + w;

    // ---- stage weights into SMEM -------------------------------------------
    for (int i = tid; i < 44800; i += TPB_B) sWc[i] = w_cell[i];
    for (int i = tid; i < 9600; i += TPB_B) {
        int cv = i / 4800, j = i % 4800;
        int oc = j / 120, j2 = j % 120, tap = j2 / 40, ic = j2 % 40;
        const float* src = cv ? w_rc : w_rh;     // src layout [oc][ic][1][3]
        sWr[i] = src[oc * 120 + ic * 3 + tap];
    }
    for (int i = tid; i < 1120; i += TPB_B) sBc[i] = b_cell[i];
    for (int i = tid; i < 80; i += TPB_B) sBr[i] = (i < 40) ? b_rh[i] : b_rc[i - 40];
    for (int i = tid; i < 1200; i += TPB_B) sHa[i] = 0.0f;  // Ha, Hb, C contiguous
    __syncthreads();

    const float* xrow = g_is + ((size_t)b * HH) * 160 * WW;

    for (int t = 0; t < HH; ++t) {
        // prefetch x_t for my (hc, w): channels hc, 40+hc, 80+hc, 120+hc
        const float* xp = xrow + (size_t)t * 160 * WW + hc * WW + wg;
        float x0 = xp[0];
        float x1 = xp[40 * WW];
        float x2 = xp[80 * WW];
        float x3 = xp[120 * WW];

        if (t > 0) {
            cluster_sync_();   // release/acquire: prior-row exports now visible
            int p = (t - 1) & 1;
            if (w == 0)
                sHa[0 * 40 + hc] = (crank > 0) ? __ldcg(&g_exp[p][b][crank - 1][1][0][hc]) : 0.0f;
            else if (w == 1)
                sC [0 * 40 + hc] = (crank > 0) ? __ldcg(&g_exp[p][b][crank - 1][1][1][hc]) : 0.0f;
            else if (w == 2)
                sHa[9 * 40 + hc] = (crank < 7) ? __ldcg(&g_exp[p][b][crank + 1][0][0][hc]) : 0.0f;
            else if (w == 3)
                sC [9 * 40 + hc] = (crank < 7) ? __ldcg(&g_exp[p][b][crank + 1][0][1][hc]) : 0.0f;
        }
        __syncthreads();

        // ---- row convs: read sHa/sC (prev row), write h into sHb -----------
        float hn = sBr[hc], cn = sBr[40 + hc];
        {
            const float4* H4  = (const float4*)sHa;
            const float4* C4  = (const float4*)sC;
            const float4* Wh  = (const float4*)(sWr + hc * 120);
            const float4* Wc2 = (const float4*)(sWr + 4800 + hc * 120);
#pragma unroll
            for (int icc = 0; icc < 10; ++icc) {
                float4 h0 = H4[w * 10 + icc];
                float4 h1 = H4[(w + 1) * 10 + icc];
                float4 h2 = H4[(w + 2) * 10 + icc];
                hn += dot4(Wh[icc], h0) + dot4(Wh[10 + icc], h1) + dot4(Wh[20 + icc], h2);
                float4 c0 = C4[w * 10 + icc];
                float4 c1 = C4[(w + 1) * 10 + icc];
                float4 c2 = C4[(w + 2) * 10 + icc];
                cn += dot4(Wc2[icc], c0) + dot4(Wc2[10 + icc], c1) + dot4(Wc2[20 + icc], c2);
            }
        }
        sHb[(1 + w) * 40 + hc] = hn;   // no sync needed: disjoint from reads

        float c = cn;
        float hval = hn;

        // ---- 7 LSTM layers (ping-pong h buffers; one barrier per layer) ----
#pragma unroll 1
        for (int l = 0; l < NLAYERS; ++l) {
            float* rbuf = (l & 1) ? sHa : sHb;
            float* wbuf = (l & 1) ? sHb : sHa;
            __syncthreads();   // prior writes to rbuf visible; prior reads of wbuf done

            float a0 = sBc[l * 160 + hc]       + x0;
            float a1 = sBc[l * 160 + 40 + hc]  + x1;
            float a2 = sBc[l * 160 + 80 + hc]  + x2;
            float a3 = sBc[l * 160 + 120 + hc] + x3;

            const float4* W0 = (const float4*)(sWc + (l * 160 + hc) * 40);
            const float4* W1 = (const float4*)(sWc + (l * 160 + 40 + hc) * 40);
            const float4* W2 = (const float4*)(sWc + (l * 160 + 80 + hc) * 40);
            const float4* W3 = (const float4*)(sWc + (l * 160 + 120 + hc) * 40);
            const float4* hv = (const float4*)(rbuf + (1 + w) * 40);
#pragma unroll
            for (int kk = 0; kk < 10; ++kk) {
                float4 h4 = hv[kk];
                a0 += dot4(W0[kk], h4);
                a1 += dot4(W1[kk], h4);
                a2 += dot4(W2[kk], h4);
                a3 += dot4(W3[kk], h4);
            }
            float iv = sigf(a0), fv = sigf(a1), ov = sigf(a2), gv = tanhf_fast(a3);
            c = fv * c + iv * gv;
            hval = ov * tanhf_fast(c);
            wbuf[(1 + w) * 40 + hc] = hval;
        }
        // layer 6 wrote sHa -> next row's row conv reads sHa. invariant holds.

        sC[(1 + w) * 40 + hc] = c;
        g_hidden[(((size_t)b * HH + t) * HIDDEN + hc) * WW + wg] = hval;

        int p2 = t & 1;
        if (w == 0) {
            g_exp[p2][b][crank][0][0][hc] = hval;
            g_exp[p2][b][crank][0][1][hc] = c;
        }
        if (w == 7) {
            g_exp[p2][b][crank][1][0][hc] = hval;
            g_exp[p2][b][crank][1][1][hc] = c;
        }
    }
}

// ===========================================================================
// Kernel C: out = relu(W_out[256x40] @ hidden + b_out). grid (64 y, 16 b).
// thread: x = tid&63, oc group = tid>>6 (64 oc each). hidden row in registers.
// ===========================================================================
__global__ void __launch_bounds__(256) kC(
    const float* __restrict__ w_out, const float* __restrict__ b_out,
    float* __restrict__ out)
{
    __shared__ float sWo[256 * 40];
    __shared__ float sBo[256];

    const int y = blockIdx.x;
    const int b = blockIdx.y;
    const int tid = threadIdx.x;

    for (int i = tid; i < 256 * 40; i += 256) sWo[i] = w_out[i];
    if (tid < 256) sBo[tid] = b_out[tid];
    __syncthreads();

    const int x   = tid & 63;
    const int ocg = tid >> 6;

    float hr[40];
    const float* hid = g_hidden + (((size_t)b * HH + y) * HIDDEN) * WW + x;
#pragma unroll
    for (int k = 0; k < 40; ++k) hr[k] = hid[k * WW];

    const int oc0 = ocg * 64;
#pragma unroll 2
    for (int oc = oc0; oc < oc0 + 64; ++oc) {
        float a = sBo[oc];
        const float4* w4 = (const float4*)&sWo[oc * 40];
#pragma unroll
        for (int kk = 0; kk < 10; ++kk) {
            float4 W = w4[kk];
            a += W.x * hr[4 * kk + 0] + W.y * hr[4 * kk + 1]
               + W.z * hr[4 * kk + 2] + W.w * hr[4 * kk + 3];
        }
        out[(((size_t)b * 256 + oc) * HH + y) * WW + x] = fmaxf(a, 0.0f);
    }
}

// ===========================================================================
// launcher
// ===========================================================================
extern "C" void kernel_launch(void* const* d_in, const int* in_sizes, int n_in,
                              void* d_out, int out_size)
{
    const float* inp    = (const float*)d_in[0];
    const float* tgt    = (const float*)d_in[1];
    const float* w_is   = (const float*)d_in[2];
    const float* b_is   = (const float*)d_in[3];
    const float* w_cis  = (const float*)d_in[4];
    const float* b_cis  = (const float*)d_in[5];
    const float* w_rh   = (const float*)d_in[6];
    const float* b_rh   = (const float*)d_in[7];
    const float* w_rc   = (const float*)d_in[8];
    const float* b_rc   = (const float*)d_in[9];
    const float* w_cell = (const float*)d_in[10];
    const float* b_cell = (const float*)d_in[11];
    const float* w_out  = (const float*)d_in[12];
    const float* b_out  = (const float*)d_in[13];
    float* out = (float*)d_out;

    cudaFuncSetAttribute((const void*)kB,
                         cudaFuncAttributeMaxDynamicSharedMemorySize, SMEMB_BYTES);

    kA<<<dim3(4, 4, 16), 256>>>(inp, tgt, w_is, b_is, w_cis, b_cis);
    kB<<<BATCH * CPB, TPB_B, SMEMB_BYTES>>>(w_cell, b_cell, w_rh, b_rh, w_rc, b_rc);
    kC<<<dim3(64, 16), 256>>>(w_out, b_out, out);
    (void)in_sizes; (void)n_in; (void)out_size;
}